// round 2
// baseline (speedup 1.0000x reference)
#include <cuda_runtime.h>
#include <cstdint>

#define GRID_D 128
#define NUM_CELLS (128*128*128)          // 2,097,152
#define INV_CELL 64.0f
#define MAX_N 1000000

#define SCAN_BLOCKS 8192                 // 8192 * 256 = 2M cells
#define SCAN_THREADS 256

// ---- scratch (device globals: no allocation allowed) ----
__device__ unsigned int g_cnt[NUM_CELLS];       // counts -> scatter cursor
__device__ unsigned int g_start[NUM_CELLS + 1]; // exclusive scan (+ total at end)
__device__ unsigned int g_bsums[SCAN_BLOCKS];
__device__ float4       g_rec[2 * MAX_N];       // {r.xyz, m}, {m*v.xyz, 0}

// ---------------- K1: per-cell particle counts ----------------
__global__ __launch_bounds__(256) void count_kernel(const float* __restrict__ pos, int n)
{
    int i = blockIdx.x * blockDim.x + threadIdx.x;
    if (i >= n) return;
    float rx = pos[3*i+0] * INV_CELL;
    float ry = pos[3*i+1] * INV_CELL;
    float rz = pos[3*i+2] * INV_CELL;
    int ix = (int)floorf(rx), iy = (int)floorf(ry), iz = (int)floorf(rz);
    int cell = iz + ix * GRID_D + iy * (GRID_D * GRID_D);
    atomicAdd(&g_cnt[cell], 1u);   // no return use -> RED
}

// ---------------- S1: block sums ----------------
__global__ __launch_bounds__(SCAN_THREADS) void scan_sum_kernel()
{
    __shared__ unsigned int s[SCAN_THREADS];
    int t = threadIdx.x;
    int i = blockIdx.x * SCAN_THREADS + t;
    unsigned int v = g_cnt[i];
    s[t] = v;
    __syncthreads();
    for (int off = SCAN_THREADS / 2; off > 0; off >>= 1) {
        if (t < off) s[t] += s[t + off];
        __syncthreads();
    }
    if (t == 0) g_bsums[blockIdx.x] = s[0];
}

// ---------------- S2: scan block sums (single block) ----------------
__global__ __launch_bounds__(1024) void scan_bsums_kernel()
{
    __shared__ unsigned int s[1024];
    int t = threadIdx.x;
    const int PER = SCAN_BLOCKS / 1024;  // 8
    unsigned int loc[PER];
    unsigned int sum = 0;
#pragma unroll
    for (int k = 0; k < PER; k++) { loc[k] = g_bsums[t * PER + k]; sum += loc[k]; }
    s[t] = sum;
    __syncthreads();
    // Hillis-Steele inclusive scan over 1024 partial sums
    for (int off = 1; off < 1024; off <<= 1) {
        unsigned int x = (t >= off) ? s[t - off] : 0u;
        __syncthreads();
        s[t] += x;
        __syncthreads();
    }
    unsigned int excl = s[t] - sum;   // exclusive prefix for this thread's chunk
#pragma unroll
    for (int k = 0; k < PER; k++) {
        unsigned int v = loc[k];
        g_bsums[t * PER + k] = excl;
        excl += v;
    }
    if (t == 1023) g_start[NUM_CELLS] = s[1023];  // total particle count
}

// ---------------- S3: per-block exclusive scan + write start/cursor ----------------
__global__ __launch_bounds__(SCAN_THREADS) void scan_write_kernel()
{
    __shared__ unsigned int s[SCAN_THREADS];
    int t = threadIdx.x;
    int i = blockIdx.x * SCAN_THREADS + t;
    unsigned int v = g_cnt[i];
    s[t] = v;
    __syncthreads();
    for (int off = 1; off < SCAN_THREADS; off <<= 1) {
        unsigned int x = (t >= off) ? s[t - off] : 0u;
        __syncthreads();
        s[t] += x;
        __syncthreads();
    }
    unsigned int excl = s[t] - v + g_bsums[blockIdx.x];
    g_start[i] = excl;
    g_cnt[i]   = excl;   // becomes scatter cursor
}

// ---------------- K3: scatter particle records into sorted order ----------------
__global__ __launch_bounds__(256) void scatter_kernel(
    const float* __restrict__ pos,
    const float* __restrict__ vel,
    const float* __restrict__ mass,
    int n)
{
    int i = blockIdx.x * blockDim.x + threadIdx.x;
    if (i >= n) return;
    float rx = pos[3*i+0] * INV_CELL;
    float ry = pos[3*i+1] * INV_CELL;
    float rz = pos[3*i+2] * INV_CELL;
    int ix = (int)floorf(rx), iy = (int)floorf(ry), iz = (int)floorf(rz);
    int cell = iz + ix * GRID_D + iy * (GRID_D * GRID_D);
    float m  = mass[i];
    float vx = vel[3*i+0], vy = vel[3*i+1], vz = vel[3*i+2];
    unsigned int idx = atomicAdd(&g_cnt[cell], 1u);
    g_rec[2*idx + 0] = make_float4(rx, ry, rz, m);
    g_rec[2*idx + 1] = make_float4(m*vx, m*vy, m*vz, 0.0f);
}

// ---------------- K4: per-cell gather (no atomics) ----------------
__global__ __launch_bounds__(SCAN_THREADS) void gather_kernel(float4* __restrict__ out)
{
    int t = blockIdx.x * SCAN_THREADS + threadIdx.x;   // == cell hash
    int cz = t & (GRID_D - 1);
    int cx = (t >> 7) & (GRID_D - 1);
    int cy = t >> 14;
    float fcx = (float)cx, fcy = (float)cy, fcz = (float)cz;

    float am = 0.f, a0 = 0.f, a1 = 0.f, a2 = 0.f;

#pragma unroll
    for (int dx = -1; dx <= 0; dx++) {
#pragma unroll
        for (int dy = -1; dy <= 0; dy++) {
            // z-pair of source cells (bx,by,cz-1) and (bx,by,cz): contiguous range
            int h = (cz - 1) + (cx + dx) * GRID_D + (cy + dy) * (GRID_D * GRID_D);
            int lo_i = min(max(h,     0), NUM_CELLS);
            int hi_i = min(max(h + 2, 0), NUM_CELLS);
            unsigned int lo = g_start[lo_i];
            unsigned int hi = g_start[hi_i];
            for (unsigned int j = lo; j < hi; j++) {
                float4 a = g_rec[2*j + 0];
                float4 b = g_rec[2*j + 1];
                float wx = fmaxf(0.0f, 1.0f - fabsf(a.x - fcx));
                float wy = fmaxf(0.0f, 1.0f - fabsf(a.y - fcy));
                float wz = fmaxf(0.0f, 1.0f - fabsf(a.z - fcz));
                float w = wx * wy * wz;
                am += w * a.w;
                a0 += w * b.x;
                a1 += w * b.y;
                a2 += w * b.z;
            }
        }
    }
    out[t] = make_float4(am, a0, a1, a2);
}

extern "C" void kernel_launch(void* const* d_in, const int* in_sizes, int n_in,
                              void* d_out, int out_size)
{
    const float* pos  = (const float*)d_in[0];
    const float* vel  = (const float*)d_in[1];
    const float* mass = (const float*)d_in[2];
    int n = in_sizes[2];

    void* cnt_ptr;
    cudaGetSymbolAddress(&cnt_ptr, g_cnt);
    cudaMemsetAsync(cnt_ptr, 0, NUM_CELLS * sizeof(unsigned int));

    int threads = 256;
    int pblocks = (n + threads - 1) / threads;

    count_kernel<<<pblocks, threads>>>(pos, n);
    scan_sum_kernel<<<SCAN_BLOCKS, SCAN_THREADS>>>();
    scan_bsums_kernel<<<1, 1024>>>();
    scan_write_kernel<<<SCAN_BLOCKS, SCAN_THREADS>>>();
    scatter_kernel<<<pblocks, threads>>>(pos, vel, mass, n);
    gather_kernel<<<SCAN_BLOCKS, SCAN_THREADS>>>((float4*)d_out);
}

// round 4
// speedup vs baseline: 1.1286x; 1.1286x over previous
#include <cuda_runtime.h>
#include <cstdint>

#define GRID_D 128
#define NUM_CELLS (128*128*128)          // 2,097,152
#define INV_CELL 64.0f
#define MAX_N 1000000

// scan configuration: 8 cells/thread, 256 threads/block -> 2048 cells/block
#define SC_THREADS 256
#define SC_PER 8
#define SC_CELLS_PER_BLOCK (SC_THREADS * SC_PER)       // 2048
#define SC_BLOCKS (NUM_CELLS / SC_CELLS_PER_BLOCK)     // 1024

// ---- scratch (device globals; no allocation allowed) ----
__device__ __align__(16) unsigned int g_cnt[NUM_CELLS];        // counts -> cursor
__device__ __align__(16) unsigned int g_start[NUM_CELLS + 4];  // exclusive scan (+total)
__device__ unsigned int g_bsums[SC_BLOCKS];
__device__ float4       g_rec[2 * MAX_N];  // {r.xyz, m}, {m*v.xyz, 0}

// ---------------- K1: per-cell particle counts ----------------
__global__ __launch_bounds__(256) void count_kernel(const float* __restrict__ pos, int n)
{
    int i = blockIdx.x * blockDim.x + threadIdx.x;
    if (i >= n) return;
    float rx = pos[3*i+0] * INV_CELL;
    float ry = pos[3*i+1] * INV_CELL;
    float rz = pos[3*i+2] * INV_CELL;
    int ix = (int)floorf(rx), iy = (int)floorf(ry), iz = (int)floorf(rz);
    int cell = iz + ix * GRID_D + iy * (GRID_D * GRID_D);
    atomicAdd(&g_cnt[cell], 1u);   // no return -> RED
}

// ---------------- S1: block sums (8 cells/thread, uint4 loads) ----------------
__global__ __launch_bounds__(SC_THREADS) void scanA_kernel()
{
    int tid = threadIdx.x;
    int base = blockIdx.x * SC_CELLS_PER_BLOCK + tid * SC_PER;
    uint4 a = *(const uint4*)(g_cnt + base);
    uint4 b = *(const uint4*)(g_cnt + base + 4);
    unsigned s = a.x + a.y + a.z + a.w + b.x + b.y + b.z + b.w;
#pragma unroll
    for (int o = 16; o > 0; o >>= 1) s += __shfl_down_sync(0xffffffffu, s, o);
    __shared__ unsigned ws[SC_THREADS / 32];
    if ((tid & 31) == 0) ws[tid >> 5] = s;
    __syncthreads();
    if (tid < SC_THREADS / 32) {
        unsigned v = ws[tid];
#pragma unroll
        for (int o = (SC_THREADS / 64); o > 0; o >>= 1)
            v += __shfl_down_sync(0xffu, v, o);
        if (tid == 0) g_bsums[blockIdx.x] = v;
    }
}

// ---------------- S2: exclusive scan of 1024 block sums (one block) ----------------
__global__ __launch_bounds__(1024) void scanB_kernel()
{
    int t = threadIdx.x;            // 0..1023, SC_BLOCKS == 1024
    unsigned v = g_bsums[t];
    unsigned x = v;
#pragma unroll
    for (int o = 1; o < 32; o <<= 1) {
        unsigned y = __shfl_up_sync(0xffffffffu, x, o);
        if ((t & 31) >= o) x += y;
    }
    __shared__ unsigned ws[32];
    if ((t & 31) == 31) ws[t >> 5] = x;
    __syncthreads();
    if (t < 32) {
        unsigned w = ws[t];
#pragma unroll
        for (int o = 1; o < 32; o <<= 1) {
            unsigned y = __shfl_up_sync(0xffffffffu, w, o);
            if (t >= o) w += y;
        }
        ws[t] = w;
    }
    __syncthreads();
    unsigned incl = x + ((t >= 32) ? ws[(t >> 5) - 1] : 0u);
    g_bsums[t] = incl - v;                       // exclusive prefix
    if (t == 1023) g_start[NUM_CELLS] = incl;    // total
}

// ---------------- S3: per-block scan; write starts + scatter cursors ----------------
__global__ __launch_bounds__(SC_THREADS) void scanC_kernel()
{
    int tid = threadIdx.x;
    int base = blockIdx.x * SC_CELLS_PER_BLOCK + tid * SC_PER;
    uint4 a = *(const uint4*)(g_cnt + base);
    uint4 b = *(const uint4*)(g_cnt + base + 4);
    unsigned c[8] = {a.x, a.y, a.z, a.w, b.x, b.y, b.z, b.w};
    unsigned tsum = 0;
#pragma unroll
    for (int k = 0; k < 8; k++) { unsigned v = c[k]; c[k] = tsum; tsum += v; }
    // block-level exclusive scan of per-thread sums
    unsigned x = tsum;
#pragma unroll
    for (int o = 1; o < 32; o <<= 1) {
        unsigned y = __shfl_up_sync(0xffffffffu, x, o);
        if ((tid & 31) >= o) x += y;
    }
    __shared__ unsigned ws[8], wso[8];
    if ((tid & 31) == 31) ws[tid >> 5] = x;
    __syncthreads();
    if (tid < 8) {
        unsigned w = ws[tid];
#pragma unroll
        for (int o = 1; o < 8; o <<= 1) {
            unsigned y = __shfl_up_sync(0xffu, w, o);
            if (tid >= o) w += y;
        }
        wso[tid] = w;
    }
    __syncthreads();
    unsigned warp_off = (tid >= 32) ? wso[(tid >> 5) - 1] : 0u;
    unsigned excl = (x - tsum) + warp_off + g_bsums[blockIdx.x];
    uint4 o0 = make_uint4(excl + c[0], excl + c[1], excl + c[2], excl + c[3]);
    uint4 o1 = make_uint4(excl + c[4], excl + c[5], excl + c[6], excl + c[7]);
    *(uint4*)(g_start + base)     = o0;
    *(uint4*)(g_start + base + 4) = o1;
    *(uint4*)(g_cnt + base)       = o0;   // cursor for scatter
    *(uint4*)(g_cnt + base + 4)   = o1;
}

// ---------------- K3: scatter particle records into cell-sorted order ----------------
__global__ __launch_bounds__(256) void scatter_kernel(
    const float* __restrict__ pos,
    const float* __restrict__ vel,
    const float* __restrict__ mass,
    int n)
{
    int i = blockIdx.x * blockDim.x + threadIdx.x;
    if (i >= n) return;
    float rx = pos[3*i+0] * INV_CELL;
    float ry = pos[3*i+1] * INV_CELL;
    float rz = pos[3*i+2] * INV_CELL;
    int ix = (int)floorf(rx), iy = (int)floorf(ry), iz = (int)floorf(rz);
    int cell = iz + ix * GRID_D + iy * (GRID_D * GRID_D);
    float m  = mass[i];
    float vx = vel[3*i+0], vy = vel[3*i+1], vz = vel[3*i+2];
    unsigned idx = atomicAdd(&g_cnt[cell], 1u);
    g_rec[2*idx + 0] = make_float4(rx, ry, rz, m);
    g_rec[2*idx + 1] = make_float4(m*vx, m*vy, m*vz, 0.0f);
}

// ---------------- K4: per-cell gather (no atomics, fully coalesced out) ------
__global__ __launch_bounds__(256) void gather_kernel(float4* __restrict__ out)
{
    int t = blockIdx.x * blockDim.x + threadIdx.x;   // cell hash; warp = 32 consecutive z
    int cz = t & (GRID_D - 1);
    int cx = (t >> 7) & (GRID_D - 1);
    int cy = t >> 14;
    float fcx = (float)cx, fcy = (float)cy, fcz = (float)cz;

    float am = 0.f, a0 = 0.f, a1 = 0.f, a2 = 0.f;

#pragma unroll
    for (int dx = -1; dx <= 0; dx++) {
#pragma unroll
        for (int dy = -1; dy <= 0; dy++) {
            int h = (cz - 1) + (cx + dx) * GRID_D + (cy + dy) * (GRID_D * GRID_D);
            int lo_i = min(max(h,     0), NUM_CELLS);
            int hi_i = min(max(h + 2, 0), NUM_CELLS);
            unsigned lo = g_start[lo_i];
            unsigned hi = g_start[hi_i];
            for (unsigned j = lo; j < hi; j++) {
                float4 a = g_rec[2*j + 0];
                float4 b = g_rec[2*j + 1];
                float wx = fmaxf(0.0f, 1.0f - fabsf(a.x - fcx));
                float wy = fmaxf(0.0f, 1.0f - fabsf(a.y - fcy));
                float wz = fmaxf(0.0f, 1.0f - fabsf(a.z - fcz));
                float w = wx * wy * wz;
                am = fmaf(w, a.w, am);
                a0 = fmaf(w, b.x, a0);
                a1 = fmaf(w, b.y, a1);
                a2 = fmaf(w, b.z, a2);
            }
        }
    }
    out[t] = make_float4(am, a0, a1, a2);
}

extern "C" void kernel_launch(void* const* d_in, const int* in_sizes, int n_in,
                              void* d_out, int out_size)
{
    const float* pos  = (const float*)d_in[0];
    const float* vel  = (const float*)d_in[1];
    const float* mass = (const float*)d_in[2];
    int n = in_sizes[2];

    void* cnt_ptr;
    cudaGetSymbolAddress(&cnt_ptr, g_cnt);
    cudaMemsetAsync(cnt_ptr, 0, NUM_CELLS * sizeof(unsigned int));

    int threads = 256;
    int pblocks = (n + threads - 1) / threads;

    count_kernel  <<<pblocks, threads>>>(pos, n);
    scanA_kernel  <<<SC_BLOCKS, SC_THREADS>>>();
    scanB_kernel  <<<1, 1024>>>();
    scanC_kernel  <<<SC_BLOCKS, SC_THREADS>>>();
    scatter_kernel<<<pblocks, threads>>>(pos, vel, mass, n);
    gather_kernel <<<NUM_CELLS / 256, 256>>>((float4*)d_out);
}

// round 5
// speedup vs baseline: 1.9739x; 1.7490x over previous
#include <cuda_runtime.h>
#include <cstdint>

#define GRID_D 128
#define NUM_CELLS (128*128*128)
#define INV_CELL 64.0f
#define PPT 4   // particles per thread

// 4 particles/thread. Loads are float4-vectorized (7 LDG.128 per 4 particles
// instead of 28 LDG.32), cutting LSU instruction dispatch ~35%. Each
// (particle, corner) is one red.global.add.v4.f32 into the [C,4] output
// (contiguous 16B-aligned float4 per cell).
__global__ __launch_bounds__(256) void p2g_kernel(
    const float4* __restrict__ pos4,   // pos viewed as float4 (3 per 4 particles)
    const float4* __restrict__ vel4,
    const float4* __restrict__ mass4,  // 1 per 4 particles
    float* __restrict__ out,
    int n)
{
    int t = blockIdx.x * blockDim.x + threadIdx.x;
    int base = t * PPT;
    if (base >= n) return;

    float px[PPT], py[PPT], pz[PPT];
    float vx[PPT], vy[PPT], vz[PPT];
    float m[PPT];

    if (base + PPT <= n) {
        // vectorized path: 12 floats pos = 3 float4, same for vel, 1 float4 mass
        float4 p0 = pos4[3*t + 0];
        float4 p1 = pos4[3*t + 1];
        float4 p2 = pos4[3*t + 2];
        px[0]=p0.x; py[0]=p0.y; pz[0]=p0.z;
        px[1]=p0.w; py[1]=p1.x; pz[1]=p1.y;
        px[2]=p1.z; py[2]=p1.w; pz[2]=p2.x;
        px[3]=p2.y; py[3]=p2.z; pz[3]=p2.w;
        float4 v0 = vel4[3*t + 0];
        float4 v1 = vel4[3*t + 1];
        float4 v2 = vel4[3*t + 2];
        vx[0]=v0.x; vy[0]=v0.y; vz[0]=v0.z;
        vx[1]=v0.w; vy[1]=v1.x; vz[1]=v1.y;
        vx[2]=v1.z; vy[2]=v1.w; vz[2]=v2.x;
        vx[3]=v2.y; vy[3]=v2.z; vz[3]=v2.w;
        float4 mm = mass4[t];
        m[0]=mm.x; m[1]=mm.y; m[2]=mm.z; m[3]=mm.w;
    } else {
        const float* pos  = (const float*)pos4;
        const float* vel  = (const float*)vel4;
        const float* mass = (const float*)mass4;
#pragma unroll
        for (int k = 0; k < PPT; k++) {
            int i = base + k;
            if (i < n) {
                px[k]=pos[3*i+0]; py[k]=pos[3*i+1]; pz[k]=pos[3*i+2];
                vx[k]=vel[3*i+0]; vy[k]=vel[3*i+1]; vz[k]=vel[3*i+2];
                m[k]=mass[i];
            } else {
                px[k]=py[k]=pz[k]=1.0f;   // maps to a valid cell
                vx[k]=vy[k]=vz[k]=0.0f;
                m[k]=0.0f;                // zero weight -> no effect
            }
        }
    }

#pragma unroll
    for (int k = 0; k < PPT; k++) {
        float rx = px[k] * INV_CELL;
        float ry = py[k] * INV_CELL;
        float rz = pz[k] * INV_CELL;
        float bx = floorf(rx), by = floorf(ry), bz = floorf(rz);
        int ix = (int)bx, iy = (int)by, iz = (int)bz;
        float fx = rx - bx, fy = ry - by, fz = rz - bz;
        float wx[2] = {1.0f - fx, fx};
        float wy[2] = {1.0f - fy, fy};
        float wz[2] = {1.0f - fz, fz};
        float mk = m[k];
        float mvx = mk * vx[k], mvy = mk * vy[k], mvz = mk * vz[k];
        int base_hash = iz + ix * GRID_D + iy * (GRID_D * GRID_D);

#pragma unroll
        for (int di = 0; di < 2; di++) {
#pragma unroll
            for (int dj = 0; dj < 2; dj++) {
#pragma unroll
                for (int dk = 0; dk < 2; dk++) {
                    float w = wx[di] * wy[dj] * wz[dk];
                    int h = base_hash + dk + di * GRID_D + dj * (GRID_D * GRID_D);
                    if ((unsigned)h < (unsigned)NUM_CELLS) {
                        float* p = out + 4ull * (unsigned)h;
                        float a0 = w * mk;
                        float a1 = w * mvx;
                        float a2 = w * mvy;
                        float a3 = w * mvz;
                        asm volatile(
                            "red.global.add.v4.f32 [%0], {%1, %2, %3, %4};"
                            :: "l"(p), "f"(a0), "f"(a1), "f"(a2), "f"(a3)
                            : "memory");
                    }
                }
            }
        }
    }
}

extern "C" void kernel_launch(void* const* d_in, const int* in_sizes, int n_in,
                              void* d_out, int out_size)
{
    const float4* pos4  = (const float4*)d_in[0];
    const float4* vel4  = (const float4*)d_in[1];
    const float4* mass4 = (const float4*)d_in[2];
    float* out = (float*)d_out;
    int n = in_sizes[2];

    cudaMemsetAsync(d_out, 0, (size_t)out_size * sizeof(float));

    int threads = 256;
    int nthreads_total = (n + PPT - 1) / PPT;
    int blocks = (nthreads_total + threads - 1) / threads;
    p2g_kernel<<<blocks, threads>>>(pos4, vel4, mass4, out, n);
}

// round 6
// speedup vs baseline: 2.4996x; 1.2664x over previous
#include <cuda_runtime.h>
#include <cstdint>

#define GRID_D 128
#define NUM_CELLS (128*128*128)
#define INV_CELL 64.0f

// 2 threads per particle (lane parity = z-corner dk). Adjacent lanes load the
// same particle (coalesced, no extra sectors) and each issues 4
// red.global.add.v4.f32 — one per (dx,dy) column. Within one RED instruction,
// lane pairs target cells h and h+1 = 32 contiguous bytes of out, so the two
// 16B payloads coalesce into a single 32B L2 sector wavefront when h is even.
// This cuts atomic wavefronts from 8/particle to ~6/particle.
__global__ __launch_bounds__(256) void p2g_kernel(
    const float* __restrict__ pos,
    const float* __restrict__ vel,
    const float* __restrict__ mass,
    float* __restrict__ out,
    int n)
{
    int t = blockIdx.x * blockDim.x + threadIdx.x;
    int p  = t >> 1;        // particle index
    int dk = t & 1;         // z-corner handled by this lane
    if (p >= n) return;

    // position in cell units
    float rx = pos[3 * p + 0] * INV_CELL;
    float ry = pos[3 * p + 1] * INV_CELL;
    float rz = pos[3 * p + 2] * INV_CELL;

    float bx = floorf(rx), by = floorf(ry), bz = floorf(rz);
    int ix = (int)bx, iy = (int)by, iz = (int)bz;

    float fx = rx - bx, fy = ry - by, fz = rz - bz;
    float wx[2] = {1.0f - fx, fx};
    float wy[2] = {1.0f - fy, fy};
    float wzk   = dk ? fz : (1.0f - fz);   // this lane's z-weight

    float m  = mass[p];
    float mvx = m * vel[3 * p + 0];
    float mvy = m * vel[3 * p + 1];
    float mvz = m * vel[3 * p + 2];

    // hash = z + x*GRID_D + y*GRID_D*GRID_D ; this lane owns z-corner iz+dk
    int base_hash = (iz + dk) + ix * GRID_D + iy * (GRID_D * GRID_D);

#pragma unroll
    for (int di = 0; di < 2; di++) {
#pragma unroll
        for (int dj = 0; dj < 2; dj++) {
            float w = wx[di] * wy[dj] * wzk;
            int h = base_hash + di * GRID_D + dj * (GRID_D * GRID_D);
            if ((unsigned)h < (unsigned)NUM_CELLS) {
                float* ptr = out + 4ull * (unsigned)h;
                float a0 = w * m;
                float a1 = w * mvx;
                float a2 = w * mvy;
                float a3 = w * mvz;
                asm volatile(
                    "red.global.add.v4.f32 [%0], {%1, %2, %3, %4};"
                    :: "l"(ptr), "f"(a0), "f"(a1), "f"(a2), "f"(a3)
                    : "memory");
            }
        }
    }
}

extern "C" void kernel_launch(void* const* d_in, const int* in_sizes, int n_in,
                              void* d_out, int out_size)
{
    const float* pos  = (const float*)d_in[0];
    const float* vel  = (const float*)d_in[1];
    const float* mass = (const float*)d_in[2];
    float* out = (float*)d_out;
    int n = in_sizes[2];   // NUM_POINTS

    cudaMemsetAsync(d_out, 0, (size_t)out_size * sizeof(float));

    int threads = 256;
    long long total = 2LL * n;               // 2 lanes per particle
    int blocks = (int)((total + threads - 1) / threads);
    p2g_kernel<<<blocks, threads>>>(pos, vel, mass, out, n);
}